// round 10
// baseline (speedup 1.0000x reference)
#include <cuda_runtime.h>
#include <cstdint>

#define EMBED     1024
#define STEPS     8
#define NF        16     // 2*STEPS features
#define GRID      444    // 3 CTAs per SM on 148-SM GB300 (persistent, no wave tail)
#define NTHREADS  256    // 256 threads * 4 dims = 1024 embed dims
#define DPT       4      // embed dims per thread (2 output f32x2 pairs)
#define MAXTOK    152    // >= ceil(65536/444) = 148

__device__ __forceinline__ unsigned long long pack2(float a, float b) {
    unsigned long long r;
    asm("mov.b64 %0, {%1, %2};" : "=l"(r) : "f"(a), "f"(b));
    return r;
}

__global__ void __launch_bounds__(NTHREADS, 3)
fractal_embed_kernel(const int*   __restrict__ token_ids,
                     const float* __restrict__ c_table,
                     const float* __restrict__ W,
                     const float* __restrict__ scale_p,
                     float*       __restrict__ out,
                     int n_tokens)
{
    // Duplicated-pair feature rows: feats_s[t] = [(f0,f0),(f1,f1),...,(f15,f15)]
    __shared__ __align__(16) float feats_s[MAXTOK][2 * NF];   // ~19 KB

    const int tid = threadIdx.x;
    const int bid = blockIdx.x;
    const float scale = *scale_p;

    // Balanced persistent slice (cheap int math, computed once)
    const int base  = n_tokens / GRID;
    const int rem   = n_tokens % GRID;
    const int start = bid * base + (bid < rem ? bid : rem);
    const int cnt   = base + (bid < rem ? 1 : 0);

    // ---- Phase A: Julia features, duplicated pairs into smem ----
    for (int t = tid; t < cnt; t += NTHREADS) {
        const int   tok = token_ids[start + t];
        const float cr  = c_table[2 * tok];
        const float ci  = c_table[2 * tok + 1];
        float zr = 0.f, zi = 0.f;
        float2* row = reinterpret_cast<float2*>(feats_s[t]);
        #pragma unroll
        for (int s = 0; s < STEPS; ++s) {
            const float nzr = zr * zr - zi * zi + cr;
            const float nzi = 2.f * zr * zi + ci;
            zr = nzr; zi = nzi;
            row[2 * s]     = make_float2(zr, zr);
            row[2 * s + 1] = make_float2(zi, zi);
        }
    }

    // ---- W output-pair-packed: w2[j][k] = (W[d0+2j][k], W[d0+2j+1][k]) * scale ----
    const int d0 = tid * DPT;
    unsigned long long w2[2][NF];            // 32 u64 = 64 regs
    #pragma unroll
    for (int j = 0; j < 2; ++j) {
        const float* wr0 = W + (size_t)(d0 + 2 * j)     * NF;
        const float* wr1 = W + (size_t)(d0 + 2 * j + 1) * NF;
        #pragma unroll
        for (int k = 0; k < NF; ++k)
            w2[j][k] = pack2(wr0[k] * scale, wr1[k] * scale);
    }
    __syncthreads();

    // ---- Phase B: chunked consumption (1 LDS.128 -> 4 FFMA2), 4 acc chains ----
    float* outp = out + (size_t)start * EMBED + d0;

    #pragma unroll 1
    for (int t = 0; t < cnt; ++t) {
        const ulonglong2* fp = reinterpret_cast<const ulonglong2*>(feats_s[t]);

        unsigned long long a00 = 0ull, a01 = 0ull, a10 = 0ull, a11 = 0ull;
        #pragma unroll
        for (int q = 0; q < 8; ++q) {
            ulonglong2 v = fp[q];            // pairs (f_{2q},f_{2q}), (f_{2q+1},f_{2q+1})
            asm("fma.rn.f32x2 %0, %1, %2, %0;" : "+l"(a00) : "l"(v.x), "l"(w2[0][2 * q]));
            asm("fma.rn.f32x2 %0, %1, %2, %0;" : "+l"(a10) : "l"(v.x), "l"(w2[1][2 * q]));
            asm("fma.rn.f32x2 %0, %1, %2, %0;" : "+l"(a01) : "l"(v.y), "l"(w2[0][2 * q + 1]));
            asm("fma.rn.f32x2 %0, %1, %2, %0;" : "+l"(a11) : "l"(v.y), "l"(w2[1][2 * q + 1]));
        }

        unsigned long long o0, o1;
        asm("add.rn.f32x2 %0, %1, %2;" : "=l"(o0) : "l"(a00), "l"(a01));
        asm("add.rn.f32x2 %0, %1, %2;" : "=l"(o1) : "l"(a10), "l"(a11));

        asm volatile("st.global.cs.v2.u64 [%0], {%1, %2};"
                     :: "l"(outp), "l"(o0), "l"(o1) : "memory");
        outp += EMBED;
    }
}

extern "C" void kernel_launch(void* const* d_in, const int* in_sizes, int n_in,
                              void* d_out, int out_size)
{
    const int*   token_ids = (const int*)  d_in[0];
    const float* c_table   = (const float*)d_in[1];
    const float* W         = (const float*)d_in[2];
    const float* scale_p   = (const float*)d_in[3];
    float*       out       = (float*)d_out;

    const int n_tokens = in_sizes[0];
    fractal_embed_kernel<<<GRID, NTHREADS>>>(token_ids, c_table, W, scale_p, out, n_tokens);
}

// round 12
// speedup vs baseline: 1.1490x; 1.1490x over previous
#include <cuda_runtime.h>
#include <cstdint>

#define EMBED     1024
#define STEPS     8
#define NF        16     // 2*STEPS features
#define NFP       8      // f32x2 feature pairs
#define GRID      444    // 3 CTAs/SM x 148 SMs, persistent balanced slices
#define NTHREADS  256    // 256 threads * 4 dims = 1024 embed dims
#define DPT       4      // embed dims per thread
#define MAXTOK    152    // >= ceil(65536/444) = 148

__device__ __forceinline__ unsigned long long pack2(float a, float b) {
    unsigned long long r;
    asm("mov.b64 %0, {%1, %2};" : "=l"(r) : "f"(a), "f"(b));
    return r;
}

__global__ void __launch_bounds__(NTHREADS, 3)
fractal_embed_kernel(const int*   __restrict__ token_ids,
                     const float* __restrict__ c_table,
                     const float* __restrict__ W,
                     const float* __restrict__ scale_p,
                     float*       __restrict__ out,
                     int n_tokens)
{
    // Plain (non-duplicated) feature rows: 16 floats = 64 B per token
    __shared__ __align__(16) float feats_s[MAXTOK][NF];   // ~9.5 KB

    const int tid = threadIdx.x;
    const int bid = blockIdx.x;
    const float scale = *scale_p;

    // Balanced persistent slice
    const int base  = n_tokens / GRID;
    const int rem   = n_tokens % GRID;
    const int start = bid * base + (bid < rem ? bid : rem);
    const int cnt   = base + (bid < rem ? 1 : 0);

    // ---- Phase A: Julia features ----
    for (int t = tid; t < cnt; t += NTHREADS) {
        const int   tok = token_ids[start + t];
        const float cr  = c_table[2 * tok];
        const float ci  = c_table[2 * tok + 1];
        float zr = 0.f, zi = 0.f;
        #pragma unroll
        for (int s = 0; s < STEPS; ++s) {
            const float nzr = zr * zr - zi * zi + cr;
            const float nzi = 2.f * zr * zi + ci;
            zr = nzr; zi = nzi;
            feats_s[t][2 * s]     = zr;
            feats_s[t][2 * s + 1] = zi;
        }
    }

    // ---- W slice: 4 rows x 16 feats, feature-pair packed, scale folded ----
    const int d0 = tid * DPT;
    unsigned long long wreg[DPT][NFP];       // 32 u64 = 64 regs
    {
        const float2* wp = reinterpret_cast<const float2*>(W + (size_t)d0 * NF);
        #pragma unroll
        for (int j = 0; j < DPT; ++j) {
            #pragma unroll
            for (int p = 0; p < NFP; ++p) {
                float2 w = wp[j * NFP + p];
                wreg[j][p] = pack2(w.x * scale, w.y * scale);
            }
        }
    }
    __syncthreads();

    // ---- Phase B: token sweep; chunked LDS.128 -> 4 FFMA2 consumption ----
    float* outp = out + (size_t)start * EMBED + d0;

    #pragma unroll 1
    for (int t = 0; t < cnt; ++t) {
        const ulonglong2* fp = reinterpret_cast<const ulonglong2*>(feats_s[t]);

        unsigned long long a0 = 0ull, a1 = 0ull, a2 = 0ull, a3 = 0ull;
        #pragma unroll
        for (int q = 0; q < 4; ++q) {        // 4x LDS.128, each feeds 8 FFMA2
            ulonglong2 v = fp[q];            // feature pairs (f4q,f4q+1),(f4q+2,f4q+3)
            asm("fma.rn.f32x2 %0, %1, %2, %0;" : "+l"(a0) : "l"(v.x), "l"(wreg[0][2 * q]));
            asm("fma.rn.f32x2 %0, %1, %2, %0;" : "+l"(a1) : "l"(v.x), "l"(wreg[1][2 * q]));
            asm("fma.rn.f32x2 %0, %1, %2, %0;" : "+l"(a2) : "l"(v.x), "l"(wreg[2][2 * q]));
            asm("fma.rn.f32x2 %0, %1, %2, %0;" : "+l"(a3) : "l"(v.x), "l"(wreg[3][2 * q]));
            asm("fma.rn.f32x2 %0, %1, %2, %0;" : "+l"(a0) : "l"(v.y), "l"(wreg[0][2 * q + 1]));
            asm("fma.rn.f32x2 %0, %1, %2, %0;" : "+l"(a1) : "l"(v.y), "l"(wreg[1][2 * q + 1]));
            asm("fma.rn.f32x2 %0, %1, %2, %0;" : "+l"(a2) : "l"(v.y), "l"(wreg[2][2 * q + 1]));
            asm("fma.rn.f32x2 %0, %1, %2, %0;" : "+l"(a3) : "l"(v.y), "l"(wreg[3][2 * q + 1]));
        }

        // Serialized unpack to minimize live temps under the 85-reg cap
        float lo, hi;
        float4 o;
        asm("mov.b64 {%0, %1}, %2;" : "=f"(lo), "=f"(hi) : "l"(a0));  o.x = lo + hi;
        asm("mov.b64 {%0, %1}, %2;" : "=f"(lo), "=f"(hi) : "l"(a1));  o.y = lo + hi;
        asm("mov.b64 {%0, %1}, %2;" : "=f"(lo), "=f"(hi) : "l"(a2));  o.z = lo + hi;
        asm("mov.b64 {%0, %1}, %2;" : "=f"(lo), "=f"(hi) : "l"(a3));  o.w = lo + hi;

        __stcs(reinterpret_cast<float4*>(outp), o);
        outp += EMBED;
    }
}

extern "C" void kernel_launch(void* const* d_in, const int* in_sizes, int n_in,
                              void* d_out, int out_size)
{
    const int*   token_ids = (const int*)  d_in[0];
    const float* c_table   = (const float*)d_in[1];
    const float* W         = (const float*)d_in[2];
    const float* scale_p   = (const float*)d_in[3];
    float*       out       = (float*)d_out;

    const int n_tokens = in_sizes[0];
    fractal_embed_kernel<<<GRID, NTHREADS>>>(token_ids, c_table, W, scale_p, out, n_tokens);
}

// round 14
// speedup vs baseline: 1.1669x; 1.0156x over previous
#include <cuda_runtime.h>
#include <cstdint>

#define EMBED     1024
#define STEPS     8
#define NF        16     // 2*STEPS features
#define NFP       8      // f32x2 feature pairs
#define GRID      444    // 3 CTAs/SM * 148 SMs; persistent balanced slices
#define NTHREADS  256    // 256 threads * 4 dims = 1024 embed dims
#define DPT       4      // embed dims per thread
#define MAXTOK    152    // >= ceil(65536/444) = 148

__device__ __forceinline__ unsigned long long pack2(float a, float b) {
    unsigned long long r;
    asm("mov.b64 %0, {%1, %2};" : "=l"(r) : "f"(a), "f"(b));
    return r;
}

__device__ __forceinline__ void slice_bounds(int bid, int n, int* start, int* cnt) {
    const int base = n / GRID;
    const int rem  = n % GRID;
    *start = bid * base + (bid < rem ? bid : rem);
    *cnt   = base + (bid < rem ? 1 : 0);
}

__global__ void __launch_bounds__(NTHREADS, 3)
fractal_embed_v11_kernel(const int*   __restrict__ token_ids,
                         const float* __restrict__ c_table,
                         const float* __restrict__ W,
                         const float* __restrict__ scale_p,
                         float*       __restrict__ out,
                         int n_tokens)
{
    // Feature rows: 16 fp32 = 64 B per token (lean layout, 4x LDS.128 per token)
    __shared__ __align__(16) float feats_s[MAXTOK][NF];   // ~9.5 KB

    const int tid = threadIdx.x;
    const float scale = *scale_p;

    int start, cnt;
    slice_bounds(blockIdx.x, n_tokens, &start, &cnt);

    // Phase A: Julia recurrence, one token per thread pass
    for (int t = tid; t < cnt; t += NTHREADS) {
        const int   tok = token_ids[start + t];
        const float cr  = c_table[2 * tok];
        const float ci  = c_table[2 * tok + 1];
        float zr = 0.f, zi = 0.f;
        #pragma unroll
        for (int s = 0; s < STEPS; ++s) {
            const float nzr = zr * zr - zi * zi + cr;
            const float nzi = 2.f * zr * zi + ci;
            zr = nzr; zi = nzi;
            feats_s[t][2 * s]     = zr;
            feats_s[t][2 * s + 1] = zi;
        }
    }

    // W slice: 4 rows x 16 feats, feature-pair packed, scale pre-folded (64 regs)
    const int d0 = tid * DPT;
    unsigned long long wreg[DPT][NFP];
    {
        const float2* wp = reinterpret_cast<const float2*>(W + (size_t)d0 * NF);
        #pragma unroll
        for (int j = 0; j < DPT; ++j) {
            #pragma unroll
            for (int p = 0; p < NFP; ++p) {
                float2 w = wp[j * NFP + p];
                wreg[j][p] = pack2(w.x * scale, w.y * scale);
            }
        }
    }
    __syncthreads();

    // Phase B: token sweep, chunked LDS.128 -> 8 FFMA2, 4 accumulator chains
    float* outp = out + (size_t)start * EMBED + d0;

    #pragma unroll 1
    for (int t = 0; t < cnt; ++t) {
        const ulonglong2* fp = reinterpret_cast<const ulonglong2*>(feats_s[t]);

        unsigned long long a0 = 0ull, a1 = 0ull, a2 = 0ull, a3 = 0ull;
        #pragma unroll
        for (int q = 0; q < 4; ++q) {
            ulonglong2 v = fp[q];   // feature pairs (f4q,f4q+1), (f4q+2,f4q+3)
            asm("fma.rn.f32x2 %0, %1, %2, %0;" : "+l"(a0) : "l"(v.x), "l"(wreg[0][2 * q]));
            asm("fma.rn.f32x2 %0, %1, %2, %0;" : "+l"(a1) : "l"(v.x), "l"(wreg[1][2 * q]));
            asm("fma.rn.f32x2 %0, %1, %2, %0;" : "+l"(a2) : "l"(v.x), "l"(wreg[2][2 * q]));
            asm("fma.rn.f32x2 %0, %1, %2, %0;" : "+l"(a3) : "l"(v.x), "l"(wreg[3][2 * q]));
            asm("fma.rn.f32x2 %0, %1, %2, %0;" : "+l"(a0) : "l"(v.y), "l"(wreg[0][2 * q + 1]));
            asm("fma.rn.f32x2 %0, %1, %2, %0;" : "+l"(a1) : "l"(v.y), "l"(wreg[1][2 * q + 1]));
            asm("fma.rn.f32x2 %0, %1, %2, %0;" : "+l"(a2) : "l"(v.y), "l"(wreg[2][2 * q + 1]));
            asm("fma.rn.f32x2 %0, %1, %2, %0;" : "+l"(a3) : "l"(v.y), "l"(wreg[3][2 * q + 1]));
        }

        // Serialized horizontal add keeps live temps minimal under the reg cap
        float lo, hi;
        float4 o;
        asm("mov.b64 {%0, %1}, %2;" : "=f"(lo), "=f"(hi) : "l"(a0));  o.x = lo + hi;
        asm("mov.b64 {%0, %1}, %2;" : "=f"(lo), "=f"(hi) : "l"(a1));  o.y = lo + hi;
        asm("mov.b64 {%0, %1}, %2;" : "=f"(lo), "=f"(hi) : "l"(a2));  o.z = lo + hi;
        asm("mov.b64 {%0, %1}, %2;" : "=f"(lo), "=f"(hi) : "l"(a3));  o.w = lo + hi;

        __stcs(reinterpret_cast<float4*>(outp), o);
        outp += EMBED;
    }
}

extern "C" void kernel_launch(void* const* d_in, const int* in_sizes, int n_in,
                              void* d_out, int out_size)
{
    const int*   token_ids = (const int*)  d_in[0];
    const float* c_table   = (const float*)d_in[1];
    const float* W         = (const float*)d_in[2];
    const float* scale_p   = (const float*)d_in[3];
    float*       out       = (float*)d_out;

    const int n_tokens = in_sizes[0];
    fractal_embed_v11_kernel<<<GRID, NTHREADS>>>(token_ids, c_table, W, scale_p, out, n_tokens);
}

// round 15
// speedup vs baseline: 1.3005x; 1.1145x over previous
#include <cuda_runtime.h>
#include <cstdint>

#define EMBED     1024
#define STEPS     8
#define NF        16     // 2*STEPS features
#define NFP       8      // f32x2 feature pairs
#define TOK_TILE  128    // tokens per CTA
#define NTHREADS  256    // 256 threads * 4 dims = 1024 embed dims
#define DPT       4      // embed dims per thread

__device__ __forceinline__ unsigned long long pack2(float a, float b) {
    unsigned long long r;
    asm("mov.b64 %0, {%1, %2};" : "=l"(r) : "f"(a), "f"(b));
    return r;
}

__device__ __forceinline__ void load_feats(const float* fs, unsigned long long* f2) {
    const ulonglong2* fp = reinterpret_cast<const ulonglong2*>(fs);
    ulonglong2 qa = fp[0], qb = fp[1], qc = fp[2], qd = fp[3];
    f2[0] = qa.x; f2[1] = qa.y; f2[2] = qb.x; f2[3] = qb.y;
    f2[4] = qc.x; f2[5] = qc.y; f2[6] = qd.x; f2[7] = qd.y;
}

__global__ void __launch_bounds__(NTHREADS, 2)
fractal_embed_v15_kernel(const int*   __restrict__ token_ids,
                         const float* __restrict__ c_table,
                         const float* __restrict__ W,
                         const float* __restrict__ scale_p,
                         float*       __restrict__ out,
                         int n_tokens)
{
    __shared__ __align__(16) float feats_s[TOK_TILE][NF];

    const int tid      = threadIdx.x;
    const int tok_base = blockIdx.x * TOK_TILE;
    if (tok_base >= n_tokens) return;
    const float scale  = *scale_p;

    // ---- Phase A: Julia features (128 threads, one token each) ----
    if (tid < TOK_TILE && tok_base + tid < n_tokens) {
        const int   tok = token_ids[tok_base + tid];
        const float cr  = c_table[2 * tok];
        const float ci  = c_table[2 * tok + 1];
        float zr = 0.f, zi = 0.f;
        #pragma unroll
        for (int s = 0; s < STEPS; ++s) {
            const float nzr = zr * zr - zi * zi + cr;
            const float nzi = 2.f * zr * zi + ci;
            zr = nzr; zi = nzi;
            feats_s[tid][2 * s]     = zr;
            feats_s[tid][2 * s + 1] = zi;
        }
    }

    // ---- W slice: 4 rows x 16 feats, scale folded, f32x2-packed (32 u64) ----
    const int d0 = tid * DPT;
    unsigned long long wreg[DPT][NFP];
    {
        const float2* wp = reinterpret_cast<const float2*>(W + (size_t)d0 * NF);
        #pragma unroll
        for (int j = 0; j < DPT; ++j) {
            #pragma unroll
            for (int p = 0; p < NFP; ++p) {
                float2 w = wp[j * NFP + p];
                wreg[j][p] = pack2(w.x * scale, w.y * scale);
            }
        }
    }
    __syncthreads();

    // ---- Phase B: 2-token interleaved sweep (8 independent FMA chains) ----
    float* outp = out + (size_t)tok_base * EMBED + d0;
    const int tmax = n_tokens - tok_base;

    if (tmax >= TOK_TILE) {
        #pragma unroll 1
        for (int t = 0; t < TOK_TILE; t += 2) {
            unsigned long long fA[NFP], fB[NFP];
            load_feats(feats_s[t],     fA);
            load_feats(feats_s[t + 1], fB);

            unsigned long long aA0 = 0ull, aA1 = 0ull, aA2 = 0ull, aA3 = 0ull;
            unsigned long long aB0 = 0ull, aB1 = 0ull, aB2 = 0ull, aB3 = 0ull;
            #pragma unroll
            for (int p = 0; p < NFP; ++p) {
                asm("fma.rn.f32x2 %0, %1, %2, %0;" : "+l"(aA0) : "l"(fA[p]), "l"(wreg[0][p]));
                asm("fma.rn.f32x2 %0, %1, %2, %0;" : "+l"(aB0) : "l"(fB[p]), "l"(wreg[0][p]));
                asm("fma.rn.f32x2 %0, %1, %2, %0;" : "+l"(aA1) : "l"(fA[p]), "l"(wreg[1][p]));
                asm("fma.rn.f32x2 %0, %1, %2, %0;" : "+l"(aB1) : "l"(fB[p]), "l"(wreg[1][p]));
                asm("fma.rn.f32x2 %0, %1, %2, %0;" : "+l"(aA2) : "l"(fA[p]), "l"(wreg[2][p]));
                asm("fma.rn.f32x2 %0, %1, %2, %0;" : "+l"(aB2) : "l"(fB[p]), "l"(wreg[2][p]));
                asm("fma.rn.f32x2 %0, %1, %2, %0;" : "+l"(aA3) : "l"(fA[p]), "l"(wreg[3][p]));
                asm("fma.rn.f32x2 %0, %1, %2, %0;" : "+l"(aB3) : "l"(fB[p]), "l"(wreg[3][p]));
            }

            float l0, h0, l1, h1, l2, h2, l3, h3;
            asm("mov.b64 {%0, %1}, %2;" : "=f"(l0), "=f"(h0) : "l"(aA0));
            asm("mov.b64 {%0, %1}, %2;" : "=f"(l1), "=f"(h1) : "l"(aA1));
            asm("mov.b64 {%0, %1}, %2;" : "=f"(l2), "=f"(h2) : "l"(aA2));
            asm("mov.b64 {%0, %1}, %2;" : "=f"(l3), "=f"(h3) : "l"(aA3));
            float4 oA = make_float4(l0 + h0, l1 + h1, l2 + h2, l3 + h3);
            asm("mov.b64 {%0, %1}, %2;" : "=f"(l0), "=f"(h0) : "l"(aB0));
            asm("mov.b64 {%0, %1}, %2;" : "=f"(l1), "=f"(h1) : "l"(aB1));
            asm("mov.b64 {%0, %1}, %2;" : "=f"(l2), "=f"(h2) : "l"(aB2));
            asm("mov.b64 {%0, %1}, %2;" : "=f"(l3), "=f"(h3) : "l"(aB3));
            float4 oB = make_float4(l0 + h0, l1 + h1, l2 + h2, l3 + h3);

            // EXPERIMENT: default write-back stores (was __stcs streaming)
            *reinterpret_cast<float4*>(outp)         = oA;
            *reinterpret_cast<float4*>(outp + EMBED) = oB;
            outp += 2 * EMBED;
        }
    } else {
        #pragma unroll 1
        for (int t = 0; t < tmax; ++t) {
            unsigned long long fA[NFP];
            load_feats(feats_s[t], fA);
            unsigned long long a0 = 0ull, a1 = 0ull, a2 = 0ull, a3 = 0ull;
            #pragma unroll
            for (int p = 0; p < NFP; ++p) {
                asm("fma.rn.f32x2 %0, %1, %2, %0;" : "+l"(a0) : "l"(fA[p]), "l"(wreg[0][p]));
                asm("fma.rn.f32x2 %0, %1, %2, %0;" : "+l"(a1) : "l"(fA[p]), "l"(wreg[1][p]));
                asm("fma.rn.f32x2 %0, %1, %2, %0;" : "+l"(a2) : "l"(fA[p]), "l"(wreg[2][p]));
                asm("fma.rn.f32x2 %0, %1, %2, %0;" : "+l"(a3) : "l"(fA[p]), "l"(wreg[3][p]));
            }
            float l0, h0, l1, h1, l2, h2, l3, h3;
            asm("mov.b64 {%0, %1}, %2;" : "=f"(l0), "=f"(h0) : "l"(a0));
            asm("mov.b64 {%0, %1}, %2;" : "=f"(l1), "=f"(h1) : "l"(a1));
            asm("mov.b64 {%0, %1}, %2;" : "=f"(l2), "=f"(h2) : "l"(a2));
            asm("mov.b64 {%0, %1}, %2;" : "=f"(l3), "=f"(h3) : "l"(a3));
            float4 o = make_float4(l0 + h0, l1 + h1, l2 + h2, l3 + h3);
            *reinterpret_cast<float4*>(outp) = o;
            outp += EMBED;
        }
    }
}

extern "C" void kernel_launch(void* const* d_in, const int* in_sizes, int n_in,
                              void* d_out, int out_size)
{
    const int*   token_ids = (const int*)  d_in[0];
    const float* c_table   = (const float*)d_in[1];
    const float* W         = (const float*)d_in[2];
    const float* scale_p   = (const float*)d_in[3];
    float*       out       = (float*)d_out;

    const int n_tokens = in_sizes[0];
    const int blocks   = (n_tokens + TOK_TILE - 1) / TOK_TILE;
    fractal_embed_v15_kernel<<<blocks, NTHREADS>>>(token_ids, c_table, W, scale_p, out, n_tokens);
}